// round 10
// baseline (speedup 1.0000x reference)
#include <cuda_runtime.h>

// Problem: B=16, S=4096.
// predicted_start[b] = argmax_s ( start[b,s] * max_{t>=s} end[b,t] )
// predicted_end[b]   = argmax_t ( end[b,t]   * max_{s<=t} start[b,s] )
// argmax = first occurrence (jnp semantics).
//
// grid = 32: blockIdx.x = 2*b + which. which==0 computes predicted_start,
// which==1 computes predicted_end.
//
// All candidate values are non-negative (products of uniforms), so float
// ordering == u32 bit-pattern ordering -> REDUX-based argmax is exact.

#define SB  16
#define SS  4096
#define NT  1024
#define VPT 4           // one float4 per array per thread, fully coalesced
#define NW  (NT / 32)   // 32 warps

#define FULL 0xffffffffu

// WHICH==1 (pred_end):   scan = start (prefix-max, ascending),  mul = end.
// WHICH==0 (pred_start): scan = end (suffix-max, descending),   mul = start.
template <int WHICH>
__device__ __forceinline__ void span_dir(const float4 s4, const float4 e4,
                                         int tid, int wid, int lane,
                                         float* wT, unsigned* rvb, unsigned* rib,
                                         float* __restrict__ out, int b)
{
    const float NEG = -3.0e38f;

    float sc[VPT], mu[VPT];
    if (WHICH) {
        sc[0]=s4.x; sc[1]=s4.y; sc[2]=s4.z; sc[3]=s4.w;
        mu[0]=e4.x; mu[1]=e4.y; mu[2]=e4.z; mu[3]=e4.w;
    } else {
        sc[0]=e4.x; sc[1]=e4.y; sc[2]=e4.z; sc[3]=e4.w;
        mu[0]=s4.x; mu[1]=s4.y; mu[2]=s4.z; mu[3]=s4.w;
    }

    // Chunk max of the scan array.
    float cm = fmaxf(fmaxf(sc[0], sc[1]), fmaxf(sc[2], sc[3]));

    // Warp total via REDUX (1 op) -> publish wT early, overlapping the scan
    // below with the other warps' arrival at the barrier.
    unsigned wmax_bits = __reduce_max_sync(FULL, __float_as_uint(cm));
    if (lane == 0) wT[wid] = __uint_as_float(wmax_bits);

    // Warp inclusive scan of chunk maxima (prefix for WHICH=1, suffix for WHICH=0).
    float ws = cm;
    #pragma unroll
    for (int off = 1; off < 32; off <<= 1) {
        if (WHICH) {
            float o = __shfl_up_sync(FULL, ws, off);
            if (lane >= off) ws = fmaxf(ws, o);
        } else {
            float o = __shfl_down_sync(FULL, ws, off);
            if (lane + off < 32) ws = fmaxf(ws, o);
        }
    }
    __syncthreads();

    // Cross-warp exclusive boundary for this warp.
    float wb = NEG;
    #pragma unroll
    for (int w = 0; w < NW; w++) {
        float v = wT[w];
        if (WHICH) { if (w < wid) wb = fmaxf(wb, v); }
        else       { if (w > wid) wb = fmaxf(wb, v); }
    }

    // Exclusive-within-warp boundary.
    float ex;
    if (WHICH) { ex = __shfl_up_sync(FULL, ws, 1);   if (lane == 0)  ex = NEG; }
    else       { ex = __shfl_down_sync(FULL, ws, 1); if (lane == 31) ex = NEG; }
    float bound = fmaxf(wb, ex);

    // Per-element running scan * mul, argmax candidate.
    //   WHICH==1: ascending, '>' keeps first occurrence.
    //   WHICH==0: descending, '>=' keeps smallest index among equals.
    float bestv = NEG; int besti = 0;
    float r = bound;
    if (WHICH) {
        #pragma unroll
        for (int i = 0; i < VPT; i++) {
            r = fmaxf(r, sc[i]);
            float v = mu[i] * r;
            if (v > bestv) { bestv = v; besti = tid * VPT + i; }
        }
    } else {
        #pragma unroll
        for (int i = VPT - 1; i >= 0; i--) {
            r = fmaxf(r, sc[i]);
            float v = mu[i] * r;
            if (v >= bestv) { bestv = v; besti = tid * VPT + i; }
        }
    }

    // Warp argmax via REDUX: max value bits, then min index among maxima.
    unsigned vb = __float_as_uint(bestv);            // bestv >= 0 -> monotone bits
    unsigned vmax = __reduce_max_sync(FULL, vb);
    unsigned icand = (vb == vmax) ? (unsigned)besti : 0xffffffffu;
    unsigned imin = __reduce_min_sync(FULL, icand);

    if (lane == 0) { rvb[wid] = vmax; rib[wid] = imin; }
    __syncthreads();

    // Warp 0 folds the 32 warp winners (same REDUX argmax).
    if (wid == 0) {
        unsigned v = rvb[lane];
        unsigned i = rib[lane];
        unsigned m = __reduce_max_sync(FULL, v);
        unsigned ic = (v == m) ? i : 0xffffffffu;
        unsigned mi = __reduce_min_sync(FULL, ic);
        if (lane == 0) {
            if (WHICH) out[SB + b] = (float)mi;   // predicted_end
            else       out[b]      = (float)mi;   // predicted_start
        }
    }
}

__global__ __launch_bounds__(NT, 1)
void probs_to_span_kernel(const float* __restrict__ start_p,
                          const float* __restrict__ end_p,
                          float* __restrict__ out)
{
    const int bid   = blockIdx.x;
    const int b     = bid >> 1;
    const int which = bid & 1;
    const int tid   = threadIdx.x;
    const int wid   = tid >> 5;
    const int lane  = tid & 31;

    const float4* sp = reinterpret_cast<const float4*>(start_p + (size_t)b * SS);
    const float4* ep = reinterpret_cast<const float4*>(end_p   + (size_t)b * SS);

    // Coalesced loads, both issued before any dependent math.
    float4 s4 = sp[tid];
    float4 e4 = ep[tid];

    __shared__ float    wT[NW];
    __shared__ unsigned rvb[NW];
    __shared__ unsigned rib[NW];

    if (which) span_dir<1>(s4, e4, tid, wid, lane, wT, rvb, rib, out, b);
    else       span_dir<0>(s4, e4, tid, wid, lane, wT, rvb, rib, out, b);
}

extern "C" void kernel_launch(void* const* d_in, const int* in_sizes, int n_in,
                              void* d_out, int out_size)
{
    const float* start_p = (const float*)d_in[0];
    const float* end_p   = (const float*)d_in[1];
    float* out           = (float*)d_out;
    probs_to_span_kernel<<<2 * SB, NT>>>(start_p, end_p, out);
}